// round 6
// baseline (speedup 1.0000x reference)
#include <cuda_runtime.h>
#include <cstddef>
#include <cstdint>

#define T_STEPS   4096
#define H_DIM     512
#define N_BATCH   32
#define V_DIM     3

#define GROUPS    4      // independent batch groups
#define BPG       8      // batches per group
#define COL_CTAS  32     // column CTAs per group
#define COLS      16     // H columns per CTA
#define NTHREADS  256
#define NWARPS    8
#define KCHUNK    (H_DIM / NWARPS)   // 64 k per warp

// ---- persistent scratch (no allocation allowed) ----
// double-buffered state: step t reads buf[t&1], writes buf[(t+1)&1]
__device__ __align__(32) float g_state[2][GROUPS][H_DIM][BPG];  // 128KB
// monotonic per-CTA step counters: flag[g][cta] == t+1  <=>  CTA finished step t
__device__ __align__(128) unsigned g_flags[GROUPS][COL_CTAS];

// Reset per replay: state := 0.01 (both buffers), flags := 0
__global__ void esn_reset_kernel() {
    int idx = blockIdx.x * blockDim.x + threadIdx.x;   // 0 .. 32767
    ((float*)g_state)[idx] = 0.01f;
    if (idx < GROUPS * COL_CTAS) ((unsigned*)g_flags)[idx] = 0u;
}

__device__ __forceinline__ uint64_t packdup(float v) {
    uint64_t r;
    asm("mov.b64 %0, {%1, %1};" : "=l"(r) : "f"(v));
    return r;
}
#define FMA2(acc, a, b) \
    asm("fma.rn.f32x2 %0, %1, %2, %0;" : "+l"(acc) : "l"(a), "l"(b))

// dynamic smem layout (floats):
// [0, 4096)        s_sm[512][8]   (state stage, 16KB)
// [4096, 5120)     red[8][8][16]  (warp partials, 4KB)
#define SMEM_FLOATS (4096 + 1024)
#define SMEM_BYTES  (SMEM_FLOATS * 4)

__global__ __launch_bounds__(NTHREADS, 1)
void esn_kernel(const float* __restrict__ X,
                const float* __restrict__ W_in,
                const float* __restrict__ W_int,
                const float* __restrict__ noise,
                float* __restrict__ out)
{
    extern __shared__ float smem[];
    float (*s_sm)[BPG]      = (float(*)[BPG])      smem;
    float (*red)[BPG][COLS] = (float(*)[BPG][COLS])(smem + 4096);

    const int tid   = threadIdx.x;
    const int g     = blockIdx.x >> 5;        // batch group 0..3
    const int myCta = blockIdx.x & 31;        // cta-in-group
    const int cbase = myCta * COLS;
    const int w     = tid >> 5;               // warp -> 64-k chunk
    const int lane  = tid & 31;

    // compute-lane decomposition: j2 = col pair (0..7), kg = 16-k subchunk (0..3)
    const int j2 = lane & 7;
    const int kg = lane >> 3;
    const int kbase = w * KCHUNK + kg * 16;

    // ---- one-time: W slice into registers as duplicated f32x2 packs ----
    uint64_t wp[16][2];
    #pragma unroll
    for (int kk = 0; kk < 16; ++kk) {
        #pragma unroll
        for (int j = 0; j < 2; ++j) {
            float wv = __ldg(&W_int[(size_t)(kbase + kk) * H_DIM + cbase + j2 * 2 + j]);
            wp[kk][j] = packdup(wv);
        }
    }

    // reducer-role constants (threads 0..127)
    const int rb = tid >> 4;             // batch-in-group
    const int rj = tid & 15;             // column-in-slice
    const int gb = g * BPG + rb;         // global batch
    const int h  = cbase + rj;           // global column
    float wi0 = 0.f, wi1 = 0.f, wi2 = 0.f;
    if (tid < 128) {
        wi0 = __ldg(&W_in[(size_t)h * V_DIM + 0]);
        wi1 = __ldg(&W_in[(size_t)h * V_DIM + 1]);
        wi2 = __ldg(&W_in[(size_t)h * V_DIM + 2]);
    }

    const unsigned* fb = &g_flags[g][0];
    unsigned* myflag = &g_flags[g][myCta];

    for (int t = 0; t < T_STEPS; ++t) {
        const float* srd = &g_state[t & 1][g][0][0];
        float*       swr = &g_state[(t & 1) ^ 1][g][0][0];

        // ---- prefetch noise & X (independent of state; issued before poll) ----
        float nval = 0.f, x0 = 0.f, x1 = 0.f, x2 = 0.f;
        if (tid < 128) {
            nval = __ldg(noise + ((size_t)t * N_BATCH + gb) * H_DIM + h);
            const float* xp = X + ((size_t)gb * T_STEPS + t) * V_DIM;
            x0 = __ldg(xp + 0); x1 = __ldg(xp + 1); x2 = __ldg(xp + 2);
        }

        // ---- coalesced acquire-poll: lane c watches CTA c's counter ----
        // flag[c] >= t  <=>  CTA c finished step t-1  (monotonic, single writer)
        if (t > 0) {
            unsigned f;
            do {
                asm volatile("ld.acquire.gpu.global.b32 %0, [%1];"
                             : "=r"(f) : "l"(fb + lane) : "memory");
            } while (!__all_sync(0xffffffffu, f >= (unsigned)t));
        }

        // ---- per-warp state stage (own 64-k slice; L2-resident via .cg) ----
        {
            const float4* src = (const float4*)srd + w * 128 + lane;
            float4*       dst = (float4*)(&s_sm[0][0]) + w * 128 + lane;
            #pragma unroll
            for (int i = 0; i < 4; ++i) {
                float4 v4 = __ldcg(src + i * 32);
                dst[i * 32] = v4;
            }
            __syncwarp();
        }

        // ---- packed f32x2 compute: 8 acc = 4 batch-pairs x 2 cols ----
        uint64_t acc[4][2];
        #pragma unroll
        for (int bp = 0; bp < 4; ++bp) { acc[bp][0] = 0ull; acc[bp][1] = 0ull; }

        const ulonglong2* srow = (const ulonglong2*)&s_sm[kbase][0]; // 2 per k-row
        #pragma unroll
        for (int kk = 0; kk < 16; ++kk) {
            ulonglong2 p0 = srow[kk * 2 + 0];   // batches 0-3 (two f32x2)
            ulonglong2 p1 = srow[kk * 2 + 1];   // batches 4-7
            FMA2(acc[0][0], p0.x, wp[kk][0]);  FMA2(acc[0][1], p0.x, wp[kk][1]);
            FMA2(acc[1][0], p0.y, wp[kk][0]);  FMA2(acc[1][1], p0.y, wp[kk][1]);
            FMA2(acc[2][0], p1.x, wp[kk][0]);  FMA2(acc[2][1], p1.x, wp[kk][1]);
            FMA2(acc[3][0], p1.y, wp[kk][0]);  FMA2(acc[3][1], p1.y, wp[kk][1]);
        }

        // unpack: a[bp][j][hh] = partial for batch 2bp+hh, col j2*2+j
        float a[4][2][2];
        #pragma unroll
        for (int bp = 0; bp < 4; ++bp)
            #pragma unroll
            for (int j = 0; j < 2; ++j)
                asm("mov.b64 {%0, %1}, %2;"
                    : "=f"(a[bp][j][0]), "=f"(a[bp][j][1]) : "l"(acc[bp][j]));

        // reduce the 4 kg subchunks within the warp (xor 8, xor 16)
        #pragma unroll
        for (int bp = 0; bp < 4; ++bp)
            #pragma unroll
            for (int j = 0; j < 2; ++j)
                #pragma unroll
                for (int hh = 0; hh < 2; ++hh) {
                    float v = a[bp][j][hh];
                    v += __shfl_xor_sync(0xffffffffu, v, 8);
                    v += __shfl_xor_sync(0xffffffffu, v, 16);
                    a[bp][j][hh] = v;
                }

        if (kg == 0) {
            #pragma unroll
            for (int bp = 0; bp < 4; ++bp)
                #pragma unroll
                for (int hh = 0; hh < 2; ++hh)
                    *(float2*)&red[w][bp * 2 + hh][j2 * 2] =
                        make_float2(a[bp][0][hh], a[bp][1][hh]);
        }
        __syncthreads();

        // ---- reduce across 8 warps, add input + noise, tanh, write ----
        if (tid < 128) {
            float sum = 0.f;
            #pragma unroll
            for (int ww = 0; ww < NWARPS; ++ww) sum += red[ww][rb][rj];
            float pre = sum + x0 * wi0 + x1 * wi1 + x2 * wi2 + 0.01f * nval;
            float sv  = tanhf(pre);
            swr[(size_t)h * BPG + rb] = sv;                           // next-step state
            out[((size_t)gb * T_STEPS + t) * H_DIM + h] = sv;         // output (N,T,H)
        }
        __syncthreads();   // all 128 state stores happen-before the release below

        // ---- contention-free release: own counter, release-store ----
        if (tid == 0) {
            asm volatile("st.release.gpu.global.b32 [%0], %1;"
                         :: "l"(myflag), "r"((unsigned)(t + 1)) : "memory");
        }
    }
}

extern "C" void kernel_launch(void* const* d_in, const int* in_sizes, int n_in,
                              void* d_out, int out_size)
{
    const float* X     = (const float*)d_in[0];   // (32, 4096, 3)
    const float* W_in  = (const float*)d_in[1];   // (512, 3)
    const float* W_int = (const float*)d_in[2];   // (512, 512)
    const float* noise = (const float*)d_in[3];   // (4096, 32, 512)
    float* out = (float*)d_out;                   // (32, 4096, 512)

    cudaFuncSetAttribute(esn_kernel, cudaFuncAttributeMaxDynamicSharedMemorySize, SMEM_BYTES);

    esn_reset_kernel<<<64, 512>>>();
    esn_kernel<<<GROUPS * COL_CTAS, NTHREADS, SMEM_BYTES>>>(X, W_in, W_int, noise, out);
}

// round 7
// speedup vs baseline: 1.4404x; 1.4404x over previous
#include <cuda_runtime.h>
#include <cstdint>
#include <cstddef>

#define T_STEPS   4096
#define H_DIM     512
#define N_BATCH   32
#define V_DIM     3

#define CLUSTER   8       // CTAs per cluster = one batch-group
#define BPG       2       // batches per group (16 groups x 2 = 32)
#define COLS      64      // H columns per CTA (8 x 64 = 512)
#define NTHREADS  256
#define NWARPS    8

// smem byte offsets
#define SOFF_STATE 0              // s_sm[2][512][2] floats = 8192 B (double-buffered full state)
#define SOFF_RED   8192           // red[8][16][4][2] floats = 4096 B
#define SOFF_BAR   12288          // bar[2], 2 x 8 B
#define SMEM_TOTAL 12304

__device__ __forceinline__ unsigned smem_u32(const void* p) {
    unsigned a;
    asm("{ .reg .u64 t; cvta.to.shared.u64 t, %1; cvt.u32.u64 %0, t; }" : "=r"(a) : "l"(p));
    return a;
}

__global__ __launch_bounds__(NTHREADS, 1) __cluster_dims__(CLUSTER, 1, 1)
void esn_kernel(const float* __restrict__ X,
                const float* __restrict__ W_in,
                const float* __restrict__ W_int,
                const float* __restrict__ noise,
                float* __restrict__ out)
{
    __shared__ __align__(16) unsigned char smem_raw[SMEM_TOTAL];

    const int tid  = threadIdx.x;
    const int lane = tid & 31;
    const int w    = tid >> 5;

    unsigned rank;
    asm("mov.u32 %0, %%cluster_ctarank;" : "=r"(rank));
    const int g = blockIdx.x >> 3;            // group id (16 groups)

    const unsigned sbase = smem_u32(smem_raw);

    // peer smem base addresses (cluster window), fixed for whole run
    unsigned pb[CLUSTER];
    #pragma unroll
    for (int r = 0; r < CLUSTER; ++r)
        asm("mapa.shared::cluster.u32 %0, %1, %2;" : "=r"(pb[r]) : "r"(sbase), "r"(r));

    // init: state buf0 := 0.01 (1024 floats = 256 float4), both mbarriers (8 arrivals)
    ((float4*)(smem_raw + SOFF_STATE))[tid] = make_float4(0.01f, 0.01f, 0.01f, 0.01f);
    if (tid == 0) {
        asm volatile("mbarrier.init.shared.b64 [%0], %1;"
                     :: "r"(sbase + SOFF_BAR + 0), "r"((unsigned)CLUSTER) : "memory");
        asm volatile("mbarrier.init.shared.b64 [%0], %1;"
                     :: "r"(sbase + SOFF_BAR + 8), "r"((unsigned)CLUSTER) : "memory");
        asm volatile("fence.mbarrier_init.release.cluster;" ::: "memory");
    }
    __syncthreads();
    asm volatile("barrier.cluster.arrive.aligned;" ::: "memory");
    asm volatile("barrier.cluster.wait.aligned;" ::: "memory");

    // ---- one-time: W_int slice into registers (512 x 64 per CTA / 256 thr = 128 f/thread) ----
    const int jg = lane & 15;                 // 4-col group (16 x 4 = 64 cols)
    const int kh = lane >> 4;                 // k half within warp chunk
    const int kb = w * 64 + kh * 32;          // this lane's first k (32 k's)
    const int cb = (int)rank * COLS + jg * 4; // this lane's first col
    float4 Wr[32];
    #pragma unroll
    for (int kk = 0; kk < 32; ++kk)
        Wr[kk] = *(const float4*)&W_int[(size_t)(kb + kk) * H_DIM + cb];

    // epilogue-role constants (threads 0..127): one (batch, col) each
    const int eb   = tid >> 6;                // batch-in-group (0/1), valid tid<128
    const int ecol = tid & 63;                // col-in-slice
    const int h    = (int)rank * COLS + ecol; // global column
    const int gb   = g * BPG + eb;            // global batch
    float wi0 = 0.f, wi1 = 0.f, wi2 = 0.f;
    if (tid < 128) {
        wi0 = __ldg(&W_in[(size_t)h * V_DIM + 0]);
        wi1 = __ldg(&W_in[(size_t)h * V_DIM + 1]);
        wi2 = __ldg(&W_in[(size_t)h * V_DIM + 2]);
    }

    float (*red)[16][4][2] = (float(*)[16][4][2])(smem_raw + SOFF_RED);

    unsigned ph0 = 0, ph1 = 0;   // per-mbarrier parity trackers

    for (int t = 0; t < T_STEPS; ++t) {
        const int cur = t & 1;
        const int nb  = cur ^ 1;

        // ---- prefetch noise & X (independent of state; issued before wait) ----
        float nval = 0.f, x0 = 0.f, x1 = 0.f, x2 = 0.f;
        if (tid < 128) {
            nval = __ldg(noise + ((size_t)t * N_BATCH + gb) * H_DIM + h);
            const float* xp = X + ((size_t)gb * T_STEPS + t) * V_DIM;
            x0 = __ldg(xp + 0); x1 = __ldg(xp + 1); x2 = __ldg(xp + 2);
        }

        // ---- wait for buf[cur] to be fully delivered (8 cluster arrivals) ----
        if (t > 0) {
            const unsigned bar = sbase + SOFF_BAR + (unsigned)cur * 8;
            const unsigned par = cur ? ph1 : ph0;
            asm volatile(
                "{\n\t.reg .pred P;\n\t"
                "W%=:\n\t"
                "mbarrier.try_wait.parity.acquire.cluster.shared::cta.b64 P, [%0], %1;\n\t"
                "@P bra D%=;\n\t"
                "bra W%=;\n\t"
                "D%=:\n\t}"
                :: "r"(bar), "r"(par) : "memory");
            if (cur) ph1 ^= 1; else ph0 ^= 1;
        }

        // ---- compute partials from local SMEM state (broadcast LDS.64) ----
        const float2* sp = (const float2*)(smem_raw + SOFF_STATE + cur * 4096) + kb;
        float a00 = 0.f, a01 = 0.f, a10 = 0.f, a11 = 0.f;
        float a20 = 0.f, a21 = 0.f, a30 = 0.f, a31 = 0.f;
        #pragma unroll
        for (int kk = 0; kk < 32; ++kk) {
            const float2 s2 = sp[kk];         // state[k][batch 0..1]
            const float4 wv = Wr[kk];         // W[k][4 cols]
            a00 += s2.x * wv.x;  a01 += s2.y * wv.x;
            a10 += s2.x * wv.y;  a11 += s2.y * wv.y;
            a20 += s2.x * wv.z;  a21 += s2.y * wv.z;
            a30 += s2.x * wv.w;  a31 += s2.y * wv.w;
        }

        // merge the two k-halves (lane ^ 16)
        a00 += __shfl_xor_sync(0xffffffffu, a00, 16);
        a01 += __shfl_xor_sync(0xffffffffu, a01, 16);
        a10 += __shfl_xor_sync(0xffffffffu, a10, 16);
        a11 += __shfl_xor_sync(0xffffffffu, a11, 16);
        a20 += __shfl_xor_sync(0xffffffffu, a20, 16);
        a21 += __shfl_xor_sync(0xffffffffu, a21, 16);
        a30 += __shfl_xor_sync(0xffffffffu, a30, 16);
        a31 += __shfl_xor_sync(0xffffffffu, a31, 16);

        if (kh == 0) {
            *(float2*)&red[w][jg][0][0] = make_float2(a00, a01);
            *(float2*)&red[w][jg][1][0] = make_float2(a10, a11);
            *(float2*)&red[w][jg][2][0] = make_float2(a20, a21);
            *(float2*)&red[w][jg][3][0] = make_float2(a30, a31);
        }
        __syncthreads();

        // ---- epilogue: cross-warp reduce, tanh, out store, push state to cluster ----
        if (tid < 128) {
            float sum = 0.f;
            #pragma unroll
            for (int ww = 0; ww < NWARPS; ++ww)
                sum += red[ww][ecol >> 2][ecol & 3][eb];
            float pre = sum + x0 * wi0 + x1 * wi1 + x2 * wi2 + 0.01f * nval;
            float sv  = tanhf(pre);
            out[((size_t)gb * T_STEPS + t) * H_DIM + h] = sv;

            if (t < T_STEPS - 1) {
                const unsigned soff = (unsigned)(SOFF_STATE + nb * 4096 + h * 8 + eb * 4);
                #pragma unroll
                for (int r = 0; r < CLUSTER; ++r)
                    asm volatile("st.shared::cluster.f32 [%0], %1;"
                                 :: "r"(pb[r] + soff), "f"(sv) : "memory");
            }
        }
        __syncthreads();   // all epilogue stores done before release-arrive; red[] WAR safe

        // ---- signal: arrive (release, cluster) on every CTA's bar[nb] ----
        if (tid == 0 && t < T_STEPS - 1) {
            const unsigned boff = (unsigned)(SOFF_BAR + nb * 8);
            #pragma unroll
            for (int r = 0; r < CLUSTER; ++r)
                asm volatile("mbarrier.arrive.release.cluster.shared::cluster.b64 _, [%0];"
                             :: "r"(pb[r] + boff) : "memory");
        }
    }

    // no remote traffic is in flight after the last step, but close out the
    // cluster cleanly before any CTA exits
    asm volatile("barrier.cluster.arrive.aligned;" ::: "memory");
    asm volatile("barrier.cluster.wait.aligned;" ::: "memory");
}

extern "C" void kernel_launch(void* const* d_in, const int* in_sizes, int n_in,
                              void* d_out, int out_size)
{
    const float* X     = (const float*)d_in[0];   // (32, 4096, 3)
    const float* W_in  = (const float*)d_in[1];   // (512, 3)
    const float* W_int = (const float*)d_in[2];   // (512, 512)
    const float* noise = (const float*)d_in[3];   // (4096, 32, 512)
    float* out = (float*)d_out;                   // (32, 4096, 512)

    // 16 clusters of 8 CTAs; clusters are mutually independent (one per batch-group)
    esn_kernel<<<16 * CLUSTER, NTHREADS>>>(X, W_in, W_int, noise, out);
}

// round 8
// speedup vs baseline: 3.8310x; 2.6597x over previous
#include <cuda_runtime.h>
#include <cstddef>
#include <cstdint>

#define T_STEPS   4096
#define H_DIM     512
#define N_BATCH   32
#define V_DIM     3

#define GROUPS    8      // independent batch groups
#define BPG       4      // batches per group
#define CPG       16     // CTAs per group
#define COLS      32     // H columns per CTA (16 x 32 = 512)
#define NTHREADS  256
#define NWARPS    8
#define KCHUNK    64     // k per warp

// ---- persistent scratch (no allocation allowed) ----
// double-buffered state: step t reads buf[t&1], writes buf[(t+1)&1]
// layout [buf][g][k][b] (batch fastest -> natural f32x2 batch pairs)
__device__ __align__(32) float g_state[2][GROUPS][H_DIM][BPG];   // 128KB
__device__ int g_bar[GROUPS][T_STEPS];                           // arrive counters

// Reset per replay: state := 0.01 (both buffers), counters := 0
__global__ void esn_reset_kernel() {
    int idx = blockIdx.x * blockDim.x + threadIdx.x;   // 0 .. 32767
    ((float*)g_state)[idx] = 0.01f;   // 2*8*512*4 = 32768 floats
    ((int*)g_bar)[idx] = 0;           // 8*4096   = 32768 ints
}

__device__ __forceinline__ uint64_t packdup(float v) {
    uint64_t r;
    asm("mov.b64 %0, {%1, %1};" : "=l"(r) : "f"(v));
    return r;
}
#define FMA2(acc, a, b) \
    asm("fma.rn.f32x2 %0, %1, %2, %0;" : "+l"(acc) : "l"(a), "l"(b))

__global__ __launch_bounds__(NTHREADS, 1)
void esn_kernel(const float* __restrict__ X,
                const float* __restrict__ W_in,
                const float* __restrict__ W_int,
                const float* __restrict__ noise,
                float* __restrict__ out)
{
    __shared__ __align__(16) float s_sm[H_DIM][BPG];        // 8KB staged state
    __shared__ __align__(16) float red[NWARPS][BPG][COLS];  // 4KB warp partials

    const int tid   = threadIdx.x;
    const int g     = blockIdx.x >> 4;        // group 0..7
    const int cbase = (blockIdx.x & 15) * COLS;
    const int w     = tid >> 5;               // warp -> 64-k chunk
    const int lane  = tid & 31;

    // compute-lane decomposition: j2 = col pair (0..15), kh = 32-k half (0/1)
    const int j2 = lane & 15;
    const int kh = lane >> 4;
    const int kbase = w * KCHUNK + kh * 32;

    // ---- one-time: W slice into registers as duplicated f32x2 packs ----
    // wp[kk][j] covers W_int[kbase+kk][cbase + j2*2 + j]
    uint64_t wp[32][2];
    #pragma unroll
    for (int kk = 0; kk < 32; ++kk) {
        #pragma unroll
        for (int j = 0; j < 2; ++j) {
            float wv = __ldg(&W_int[(size_t)(kbase + kk) * H_DIM + cbase + j2 * 2 + j]);
            wp[kk][j] = packdup(wv);
        }
    }

    // reducer-role constants (threads 0..127): one (batch, col) each
    const int rj = tid & 31;             // column-in-slice
    const int rb = (tid >> 5) & 3;       // batch-in-group (valid for tid<128)
    const int gb = g * BPG + rb;         // global batch
    const int h  = cbase + rj;           // global column
    float wi0 = 0.f, wi1 = 0.f, wi2 = 0.f;
    if (tid < 128) {
        wi0 = __ldg(&W_in[(size_t)h * V_DIM + 0]);
        wi1 = __ldg(&W_in[(size_t)h * V_DIM + 1]);
        wi2 = __ldg(&W_in[(size_t)h * V_DIM + 2]);
    }

    for (int t = 0; t < T_STEPS; ++t) {
        const float* srd = &g_state[t & 1][g][0][0];
        float*       swr = &g_state[(t & 1) ^ 1][g][0][0];

        // ---- prefetch noise & X (independent of state; issued before poll) ----
        float nval = 0.f, x0 = 0.f, x1 = 0.f, x2 = 0.f;
        if (tid < 128) {
            nval = __ldg(noise + ((size_t)t * N_BATCH + gb) * H_DIM + h);
            const float* xp = X + ((size_t)gb * T_STEPS + t) * V_DIM;
            x0 = __ldg(xp + 0); x1 = __ldg(xp + 1); x2 = __ldg(xp + 2);
        }

        // ---- warp0-only acquire-poll on the single group counter ----
        if (t > 0 && w == 0) {
            const int* barp = &g_bar[g][t - 1];
            int v;
            do {
                asm volatile("ld.acquire.gpu.global.b32 %0, [%1];"
                             : "=r"(v) : "l"(barp) : "memory");
            } while (v < CPG);
        }
        __syncthreads();   // B1: broadcasts the acquire to all warps

        // ---- per-warp state stage (own 64-k slice = 64 float4; .cg) ----
        {
            const float4* src = (const float4*)srd + w * 64 + lane;
            float4*       dst = (float4*)(&s_sm[0][0]) + w * 64 + lane;
            float4 v0 = __ldcg(src);
            float4 v1 = __ldcg(src + 32);
            dst[0]  = v0;
            dst[32] = v1;
            __syncwarp();
        }

        // ---- packed f32x2 compute: 4 acc = 2 cols x 2 batch-pairs ----
        uint64_t acc[2][2];
        acc[0][0] = 0ull; acc[0][1] = 0ull; acc[1][0] = 0ull; acc[1][1] = 0ull;

        const ulonglong2* srow = (const ulonglong2*)&s_sm[kbase][0]; // 1 per k-row
        #pragma unroll
        for (int kk = 0; kk < 32; ++kk) {
            const ulonglong2 p = srow[kk];   // (batch01, batch23) as two f32x2
            FMA2(acc[0][0], p.x, wp[kk][0]);  FMA2(acc[1][0], p.x, wp[kk][1]);
            FMA2(acc[0][1], p.y, wp[kk][0]);  FMA2(acc[1][1], p.y, wp[kk][1]);
        }

        // unpack: a[j][b] = partial for col j2*2+j, batch b
        float a[2][4];
        #pragma unroll
        for (int j = 0; j < 2; ++j) {
            asm("mov.b64 {%0, %1}, %2;" : "=f"(a[j][0]), "=f"(a[j][1]) : "l"(acc[j][0]));
            asm("mov.b64 {%0, %1}, %2;" : "=f"(a[j][2]), "=f"(a[j][3]) : "l"(acc[j][1]));
        }

        // merge the two k-halves (lane ^ 16)
        #pragma unroll
        for (int j = 0; j < 2; ++j)
            #pragma unroll
            for (int b = 0; b < 4; ++b)
                a[j][b] += __shfl_xor_sync(0xffffffffu, a[j][b], 16);

        if (kh == 0) {
            #pragma unroll
            for (int b = 0; b < 4; ++b)
                *(float2*)&red[w][b][j2 * 2] = make_float2(a[0][b], a[1][b]);
        }
        __syncthreads();   // B2: red[] complete

        // ---- reduce across 8 warps, add input + noise, tanh, write ----
        if (tid < 128) {
            float sum = 0.f;
            #pragma unroll
            for (int ww = 0; ww < NWARPS; ++ww) sum += red[ww][rb][rj];
            float pre = sum + x0 * wi0 + x1 * wi1 + x2 * wi2 + 0.01f * nval;
            float sv  = tanhf(pre);
            swr[(size_t)h * BPG + rb] = sv;                           // next-step state
            out[((size_t)gb * T_STEPS + t) * H_DIM + h] = sv;         // output (N,T,H)
        }
        __syncthreads();   // B3: state stores done before release; red[] WAR safe

        // ---- release: fence + single atomic arrive on this step's counter ----
        if (tid == 0) {
            __threadfence();
            atomicAdd(&g_bar[g][t], 1);
        }
    }
}

extern "C" void kernel_launch(void* const* d_in, const int* in_sizes, int n_in,
                              void* d_out, int out_size)
{
    const float* X     = (const float*)d_in[0];   // (32, 4096, 3)
    const float* W_in  = (const float*)d_in[1];   // (512, 3)
    const float* W_int = (const float*)d_in[2];   // (512, 512)
    const float* noise = (const float*)d_in[3];   // (4096, 32, 512)
    float* out = (float*)d_out;                   // (32, 4096, 512)

    esn_reset_kernel<<<64, 512>>>();
    esn_kernel<<<GROUPS * CPG, NTHREADS>>>(X, W_in, W_int, noise, out);
}

// round 9
// speedup vs baseline: 4.4462x; 1.1606x over previous
#include <cuda_runtime.h>
#include <cstddef>
#include <cstdint>

#define T_STEPS   4096
#define H_DIM     512
#define N_BATCH   32
#define V_DIM     3

#define GROUPS    8      // independent batch groups
#define BPG       4      // batches per group
#define CPG       16     // CTAs per group
#define COLS      32     // H columns per CTA (16 x 32 = 512)
#define NTHREADS  256
#define NWARPS    8
#define KCHUNK    64     // k per warp

// ---- persistent scratch (no allocation allowed) ----
// double-buffered state: step t reads buf[t&1], writes buf[(t+1)&1]
// layout [buf][g][k][b] (batch fastest -> natural f32x2 batch pairs)
__device__ __align__(32) float g_state[2][GROUPS][H_DIM][BPG];   // 128KB
// one 128B line PER STEP per group: pollers of flag[t-1] never touch the
// line producers are RED-ing (flag[t])
__device__ __align__(128) int g_bar[GROUPS][T_STEPS][32];        // 4MB

// Reset per replay: state := 0.01 (both buffers), counters := 0
__global__ void esn_reset_kernel() {
    const size_t stride = (size_t)gridDim.x * blockDim.x;
    size_t i0 = blockIdx.x * (size_t)blockDim.x + threadIdx.x;
    // state: 2*8*512*4 = 32768 floats
    for (size_t i = i0; i < 32768; i += stride)
        ((float*)g_state)[i] = 0.01f;
    // flags: 8*4096*32 ints
    const size_t nbar = (size_t)GROUPS * T_STEPS * 32;
    for (size_t i = i0; i < nbar; i += stride)
        ((int*)g_bar)[i] = 0;
}

__device__ __forceinline__ uint64_t packdup(float v) {
    uint64_t r;
    asm("mov.b64 %0, {%1, %1};" : "=l"(r) : "f"(v));
    return r;
}
#define FMA2(acc, a, b) \
    asm("fma.rn.f32x2 %0, %1, %2, %0;" : "+l"(acc) : "l"(a), "l"(b))

__global__ __launch_bounds__(NTHREADS, 1)
void esn_kernel(const float* __restrict__ X,
                const float* __restrict__ W_in,
                const float* __restrict__ W_int,
                const float* __restrict__ noise,
                float* __restrict__ out)
{
    __shared__ __align__(16) float s_sm[H_DIM][BPG];        // 8KB staged state
    __shared__ __align__(16) float red[NWARPS][BPG][COLS];  // 4KB warp partials

    const int tid   = threadIdx.x;
    const int g     = blockIdx.x >> 4;        // group 0..7
    const int cbase = (blockIdx.x & 15) * COLS;
    const int w     = tid >> 5;               // warp -> 64-k chunk
    const int lane  = tid & 31;

    // compute-lane decomposition: j2 = col pair (0..15), kh = 32-k half (0/1)
    const int j2 = lane & 15;
    const int kh = lane >> 4;
    const int kbase = w * KCHUNK + kh * 32;

    // ---- one-time: W slice into registers as duplicated f32x2 packs ----
    uint64_t wp[32][2];
    #pragma unroll
    for (int kk = 0; kk < 32; ++kk) {
        #pragma unroll
        for (int j = 0; j < 2; ++j) {
            float wv = __ldg(&W_int[(size_t)(kbase + kk) * H_DIM + cbase + j2 * 2 + j]);
            wp[kk][j] = packdup(wv);
        }
    }

    // reducer-role constants (threads 0..127): one (batch, col) each
    const int rj = tid & 31;             // column-in-slice
    const int rb = (tid >> 5) & 3;       // batch-in-group (valid for tid<128)
    const int gb = g * BPG + rb;         // global batch
    const int h  = cbase + rj;           // global column
    float wi0 = 0.f, wi1 = 0.f, wi2 = 0.f;
    if (tid < 128) {
        wi0 = __ldg(&W_in[(size_t)h * V_DIM + 0]);
        wi1 = __ldg(&W_in[(size_t)h * V_DIM + 1]);
        wi2 = __ldg(&W_in[(size_t)h * V_DIM + 2]);
    }

    for (int t = 0; t < T_STEPS; ++t) {
        const float* srd = &g_state[t & 1][g][0][0];
        float*       swr = &g_state[(t & 1) ^ 1][g][0][0];

        // ---- prefetch noise & X (independent of state; issued before poll) ----
        float nval = 0.f, x0 = 0.f, x1 = 0.f, x2 = 0.f;
        if (tid < 128) {
            nval = __ldg(noise + ((size_t)t * N_BATCH + gb) * H_DIM + h);
            const float* xp = X + ((size_t)gb * T_STEPS + t) * V_DIM;
            x0 = __ldg(xp + 0); x1 = __ldg(xp + 1); x2 = __ldg(xp + 2);
        }

        // ---- per-warp acquire-poll (converged load, dedicated flag line) ----
        if (t > 0) {
            const int* barp = &g_bar[g][t - 1][0];
            int v;
            do {
                asm volatile("ld.acquire.gpu.global.b32 %0, [%1];"
                             : "=r"(v) : "l"(barp) : "memory");
            } while (v < CPG);
        }

        // ---- per-warp state stage (own 64-k slice = 64 float4; .cg) ----
        {
            const float4* src = (const float4*)srd + w * 64 + lane;
            float4*       dst = (float4*)(&s_sm[0][0]) + w * 64 + lane;
            float4 v0 = __ldcg(src);
            float4 v1 = __ldcg(src + 32);
            dst[0]  = v0;
            dst[32] = v1;
            __syncwarp();
        }

        // ---- packed f32x2 compute: 4 acc = 2 cols x 2 batch-pairs ----
        uint64_t acc[2][2];
        acc[0][0] = 0ull; acc[0][1] = 0ull; acc[1][0] = 0ull; acc[1][1] = 0ull;

        const ulonglong2* srow = (const ulonglong2*)&s_sm[kbase][0]; // 1 per k-row
        #pragma unroll
        for (int kk = 0; kk < 32; ++kk) {
            const ulonglong2 p = srow[kk];   // (batch01, batch23) as two f32x2
            FMA2(acc[0][0], p.x, wp[kk][0]);  FMA2(acc[1][0], p.x, wp[kk][1]);
            FMA2(acc[0][1], p.y, wp[kk][0]);  FMA2(acc[1][1], p.y, wp[kk][1]);
        }

        // unpack: a[j][b] = partial for col j2*2+j, batch b
        float a[2][4];
        #pragma unroll
        for (int j = 0; j < 2; ++j) {
            asm("mov.b64 {%0, %1}, %2;" : "=f"(a[j][0]), "=f"(a[j][1]) : "l"(acc[j][0]));
            asm("mov.b64 {%0, %1}, %2;" : "=f"(a[j][2]), "=f"(a[j][3]) : "l"(acc[j][1]));
        }

        // merge the two k-halves (lane ^ 16)
        #pragma unroll
        for (int j = 0; j < 2; ++j)
            #pragma unroll
            for (int b = 0; b < 4; ++b)
                a[j][b] += __shfl_xor_sync(0xffffffffu, a[j][b], 16);

        if (kh == 0) {
            #pragma unroll
            for (int b = 0; b < 4; ++b)
                *(float2*)&red[w][b][j2 * 2] = make_float2(a[0][b], a[1][b]);
        }
        __syncthreads();   // B2: red[] complete

        // ---- reduce across 8 warps, add input + noise, tanh; publish state ----
        float sv = 0.f;
        if (tid < 128) {
            float sum = 0.f;
            #pragma unroll
            for (int ww = 0; ww < NWARPS; ++ww) sum += red[ww][rb][rj];
            float pre = sum + x0 * wi0 + x1 * wi1 + x2 * wi2 + 0.01f * nval;
            sv = tanhf(pre);
            swr[(size_t)h * BPG + rb] = sv;                           // next-step state
        }
        __syncthreads();   // B3: all state stores before release; red[] WAR safe

        // ---- fire-and-forget release: red.release on this step's own line ----
        if (tid == 0 && t < T_STEPS - 1) {
            int one = 1;
            asm volatile("red.release.gpu.global.add.s32 [%0], %1;"
                         :: "l"(&g_bar[g][t][0]), "r"(one) : "memory");
        }

        // ---- out store off the critical path (overlaps next step's poll) ----
        if (tid < 128)
            out[((size_t)gb * T_STEPS + t) * H_DIM + h] = sv;
    }
}

extern "C" void kernel_launch(void* const* d_in, const int* in_sizes, int n_in,
                              void* d_out, int out_size)
{
    const float* X     = (const float*)d_in[0];   // (32, 4096, 3)
    const float* W_in  = (const float*)d_in[1];   // (512, 3)
    const float* W_int = (const float*)d_in[2];   // (512, 512)
    const float* noise = (const float*)d_in[3];   // (4096, 32, 512)
    float* out = (float*)d_out;                   // (32, 4096, 512)

    esn_reset_kernel<<<512, 512>>>();
    esn_kernel<<<GROUPS * CPG, NTHREADS>>>(X, W_in, W_int, noise, out);
}